// round 1
// baseline (speedup 1.0000x reference)
#include <cuda_runtime.h>

#define BB 32
#define KK 10
#define NN 128
#define FF 512
#define NUM_ITERS 30
#define LRc 0.5f
#define RHOc 10.0f

// ---- scratch (static device globals: allocation-free) ----
static __device__ float g_C[BB * NN * NN];                 // 2 MB  (G, then C in-place)
static __device__ float g_Z[(size_t)BB * KK * NN * NN];    // 21 MB (max-shifted logits)
static __device__ float g_P[BB * KK * NN];                 // column sums p
static __device__ float g_cost[BB * KK];
static __device__ float g_w[BB * KK * NN];                 // min-gradient weights
static __device__ float g_a[BB * KK];                      // 2*RHO*pen
static __device__ float g_xn[BB * NN];
static __device__ int   g_ticket[BB];                      // zero-init; reset each launch

__device__ __forceinline__ float wsum(float v) {
#pragma unroll
    for (int o = 16; o; o >>= 1) v += __shfl_xor_sync(0xffffffffu, v, o);
    return v;
}
__device__ __forceinline__ float wmax(float v) {
#pragma unroll
    for (int o = 16; o; o >>= 1) v = fmaxf(v, __shfl_xor_sync(0xffffffffu, v, o));
    return v;
}

// ---- xn[b][i] = sum_f X^2 ----
__global__ void xn_kernel(const float* __restrict__ X) {
    int b = blockIdx.x;
    int w = threadIdx.x >> 5, lane = threadIdx.x & 31;
    for (int l = w; l < NN; l += 8) {
        const float4* xr = (const float4*)(X + ((size_t)b * NN + l) * FF);
        float acc = 0.f;
#pragma unroll
        for (int q = 0; q < FF / 128; q++) {
            float4 v = xr[lane + 32 * q];
            acc += v.x * v.x + v.y * v.y + v.z * v.z + v.w * v.w;
        }
        acc = wsum(acc);
        if (lane == 0) g_xn[b * NN + l] = acc;
    }
}

// ---- G = X X^T per b, 64x64 tiles ----
__global__ void gemm_kernel(const float* __restrict__ X) {
    int b = blockIdx.z;
    int ti = blockIdx.y * 64, tj = blockIdx.x * 64;
    __shared__ float As[16][64];
    __shared__ float Bs[16][64];
    const float* Xb = X + (size_t)b * NN * FF;
    int t = threadIdx.x;
    int lr = t >> 2, lq = t & 3;
    int tx = t & 15, ty = t >> 4;
    float acc[4][4];
#pragma unroll
    for (int i = 0; i < 4; i++)
#pragma unroll
        for (int j = 0; j < 4; j++) acc[i][j] = 0.f;

    for (int kc = 0; kc < FF; kc += 16) {
        float4 av = *(const float4*)(Xb + (size_t)(ti + lr) * FF + kc + lq * 4);
        float4 bv = *(const float4*)(Xb + (size_t)(tj + lr) * FF + kc + lq * 4);
        if (kc) __syncthreads();
        As[lq * 4 + 0][lr] = av.x; As[lq * 4 + 1][lr] = av.y;
        As[lq * 4 + 2][lr] = av.z; As[lq * 4 + 3][lr] = av.w;
        Bs[lq * 4 + 0][lr] = bv.x; Bs[lq * 4 + 1][lr] = bv.y;
        Bs[lq * 4 + 2][lr] = bv.z; Bs[lq * 4 + 3][lr] = bv.w;
        __syncthreads();
#pragma unroll
        for (int kk = 0; kk < 16; kk++) {
            float4 af = *(const float4*)&As[kk][ty * 4];
            float4 bf = *(const float4*)&Bs[kk][tx * 4];
            float a[4] = {af.x, af.y, af.z, af.w};
            float bb[4] = {bf.x, bf.y, bf.z, bf.w};
#pragma unroll
            for (int i = 0; i < 4; i++)
#pragma unroll
                for (int j = 0; j < 4; j++) acc[i][j] = fmaf(a[i], bb[j], acc[i][j]);
        }
    }
#pragma unroll
    for (int i = 0; i < 4; i++) {
        float4 o; o.x = acc[i][0]; o.y = acc[i][1]; o.z = acc[i][2]; o.w = acc[i][3];
        *(float4*)(g_C + ((size_t)b * NN + ti + ty * 4 + i) * NN + tj + tx * 4) = o;
    }
}

// ---- C = clip(dist - diag_col, 0), in-place over G ----
__global__ void finC_kernel() {
    int b = blockIdx.x;
    __shared__ float xns[NN], dgv[NN];
    float* Gb = g_C + (size_t)b * NN * NN;
    for (int j = threadIdx.x; j < NN; j += 256) {
        float xj = g_xn[b * NN + j];
        xns[j] = xj;
        dgv[j] = xj + xj - 2.0f * Gb[j * NN + j];   // numerical diag of dist
    }
    __syncthreads();
    for (int idx = threadIdx.x; idx < NN * NN; idx += 256) {
        int i = idx >> 7, j = idx & 127;
        float dist = xns[i] + xns[j] - 2.0f * Gb[idx];
        Gb[idx] = fmaxf(dist - dgv[j], 0.0f);
    }
}

// ---- per-b epilogue: min over k (with JAX tie split), penalty coeff ----
__device__ __forceinline__ void epilogue_b(int b, const float* __restrict__ theta) {
    int tid = threadIdx.x;
    if (tid < NN) {
        float pv[KK];
        float mn = 3.402823466e38f;
#pragma unroll
        for (int k = 0; k < KK; k++) {
            pv[k] = __ldcg(&g_P[(b * KK + k) * NN + tid]);
            mn = fminf(mn, pv[k]);
        }
        float cnt = 0.f;
#pragma unroll
        for (int k = 0; k < KK; k++) cnt += (pv[k] == mn) ? 1.f : 0.f;
        float iv = 1.f / cnt;
#pragma unroll
        for (int k = 0; k < KK; k++)
            g_w[(b * KK + k) * NN + tid] = (pv[k] == mn) ? iv : 0.f;
    } else if (tid < NN + KK) {
        int k = tid - NN;
        float pen = __ldcg(&g_cost[b * KK + k]) - theta[b * KK + k];
        g_a[b * KK + k] = (pen > 0.f) ? (2.f * RHOc * pen) : 0.f;
    }
    if (tid == 0) g_ticket[b] = 0;
}

__device__ __forceinline__ void ticket_and_epilogue(int b, const float* __restrict__ theta,
                                                    int* flag_s) {
    __threadfence();
    __syncthreads();
    if (threadIdx.x == 0) {
        int old = atomicAdd(&g_ticket[b], 1);
        *flag_s = (old == KK - 1) ? 1 : 0;
    }
    __syncthreads();
    if (*flag_s) {
        __threadfence();
        epilogue_b(b, theta);
    }
}

// ---- init: Z=0, p0, cost0, then epilogue ----
__global__ void init_kernel(const float* __restrict__ Q, const float* __restrict__ theta) {
    int k = blockIdx.x, b = blockIdx.y;
    int tid = threadIdx.x, w = tid >> 5, lane = tid & 31;
    const float* Qr = Q + (b * KK + k) * NN;
    __shared__ float sq_s, sc_s;
    __shared__ int flag_s;
    if (tid == 0) { sq_s = 0.f; sc_s = 0.f; }
    __syncthreads();

    float4* Zp = (float4*)(g_Z + (size_t)(b * KK + k) * NN * NN);
    float4 z4 = make_float4(0.f, 0.f, 0.f, 0.f);
    for (int i = tid; i < NN * NN / 4; i += 256) Zp[i] = z4;

    float sq = 0.f, sc = 0.f;
    for (int l = w; l < NN; l += 8) {
        float ql = Qr[l];
        const float4* Cr = (const float4*)(g_C + ((size_t)b * NN + l) * NN);
        float4 c = Cr[lane];
        float rs = wsum(c.x + c.y + c.z + c.w);
        if (lane == 0) { sq += ql; sc += ql * rs; }
    }
    if (lane == 0) { atomicAdd(&sq_s, sq); atomicAdd(&sc_s, sc); }
    __syncthreads();
    float p0 = sq_s * (1.0f / NN);
    for (int j = tid; j < NN; j += 256) g_P[(b * KK + k) * NN + j] = p0;
    if (tid == 0) g_cost[b * KK + k] = sc_s * (1.0f / NN);

    ticket_and_epilogue(b, theta, &flag_s);
}

// ---- one mirror-ascent iteration, fully fused ----
__global__ void iter_kernel(const float* __restrict__ Q, const float* __restrict__ theta,
                            float* __restrict__ p_out, int last) {
    int k = blockIdx.x, b = blockIdx.y;
    int tid = threadIdx.x, w = tid >> 5, lane = tid & 31;
    __shared__ float w_s[NN];
    __shared__ float p_s[NN];
    __shared__ float cost_s;
    __shared__ int flag_s;

    const float* Qr = Q + (b * KK + k) * NN;
    float a = g_a[b * KK + k];
    for (int j = tid; j < NN; j += 256) {
        w_s[j] = g_w[(b * KK + k) * NN + j];
        p_s[j] = 0.f;
    }
    if (tid == 0) cost_s = 0.f;
    __syncthreads();

    float* Zbk = g_Z + (size_t)(b * KK + k) * NN * NN;
    const float* Cb = g_C + (size_t)b * NN * NN;

    float pa0 = 0.f, pa1 = 0.f, pa2 = 0.f, pa3 = 0.f;
    float cacc = 0.f;
    int j4 = lane * 4;

    for (int l = w; l < NN; l += 8) {
        float ql = Qr[l];
        float4 z  = *(float4*)(Zbk + l * NN + j4);
        float4 c4 = *(const float4*)(Cb + l * NN + j4);

        // s = softmax(z): stored z is max-shifted, max = 0 -> exp args <= 0
        float e0 = expf(z.x), e1 = expf(z.y), e2 = expf(z.z), e3 = expf(z.w);
        float r = wsum(e0 + e1 + e2 + e3);
        float ir = 1.0f / r;
        float s0 = e0 * ir, s1 = e1 * ir, s2 = e2 * ir, s3 = e3 * ir;

        float4 wv = *(const float4*)&w_s[j4];
        float G0 = fmaf(-a, c4.x, wv.x);
        float G1 = fmaf(-a, c4.y, wv.y);
        float G2 = fmaf(-a, c4.z, wv.z);
        float G3 = fmaf(-a, c4.w, wv.w);

        float m = wsum(s0 * G0 + s1 * G1 + s2 * G2 + s3 * G3);

        float lq = LRc * ql;
        float zn0 = z.x + lq * s0 * (G0 - m);
        float zn1 = z.y + lq * s1 * (G1 - m);
        float zn2 = z.z + lq * s2 * (G2 - m);
        float zn3 = z.w + lq * s3 * (G3 - m);

        float mz = wmax(fmaxf(fmaxf(zn0, zn1), fmaxf(zn2, zn3)));
        zn0 -= mz; zn1 -= mz; zn2 -= mz; zn3 -= mz;

        float f0 = expf(zn0), f1 = expf(zn1), f2 = expf(zn2), f3 = expf(zn3);
        float r2 = wsum(f0 + f1 + f2 + f3);
        float ir2 = 1.0f / r2;
        float t0 = f0 * ir2, t1 = f1 * ir2, t2 = f2 * ir2, t3 = f3 * ir2;

        if (!last)
            *(float4*)(Zbk + l * NN + j4) = make_float4(zn0, zn1, zn2, zn3);

        pa0 += ql * t0; pa1 += ql * t1; pa2 += ql * t2; pa3 += ql * t3;
        cacc += ql * (t0 * c4.x + t1 * c4.y + t2 * c4.z + t3 * c4.w);
    }

    atomicAdd(&p_s[j4 + 0], pa0);
    atomicAdd(&p_s[j4 + 1], pa1);
    atomicAdd(&p_s[j4 + 2], pa2);
    atomicAdd(&p_s[j4 + 3], pa3);
    cacc = wsum(cacc);
    if (lane == 0) atomicAdd(&cost_s, cacc);
    __syncthreads();

    if (last) {
        for (int j = tid; j < NN; j += 256)
            p_out[(b * KK + k) * NN + j] = p_s[j];
        return;
    }
    for (int j = tid; j < NN; j += 256)
        g_P[(b * KK + k) * NN + j] = p_s[j];
    if (tid == 0) g_cost[b * KK + k] = cost_s;

    ticket_and_epilogue(b, theta, &flag_s);
}

extern "C" void kernel_launch(void* const* d_in, const int* in_sizes, int n_in,
                              void* d_out, int out_size) {
    const float* X     = (const float*)d_in[0];  // [32,128,512]
    const float* Qp    = (const float*)d_in[1];  // [32,10,128]
    const float* theta = (const float*)d_in[2];  // [32,10]
    float* out = (float*)d_out;                  // [32,10,128]

    xn_kernel<<<BB, 256>>>(X);
    gemm_kernel<<<dim3(2, 2, BB), 256>>>(X);
    finC_kernel<<<BB, 256>>>();
    init_kernel<<<dim3(KK, BB), 256>>>(Qp, theta);
    for (int t = 0; t < NUM_ITERS; t++) {
        int last = (t == NUM_ITERS - 1);
        iter_kernel<<<dim3(KK, BB), 256>>>(Qp, theta, out, last);
    }
}